// round 15
// baseline (speedup 1.0000x reference)
#include <cuda_runtime.h>

#define H  64
#define LL 2048
#define VOCAB 64
#define NBLK 64
#define FULL 0xffffffffu

// -------- device-global scratch (no runtime allocation allowed) --------
__device__ __align__(16) float g_ktab[VOCAB * H];    // normalized k per vocab id
__device__ __align__(16) float g_vtab[VOCAB * H];    // v per vocab id
__device__ __align__(16) float g_qtab[VOCAB * H];    // q per vocab id
__device__ __align__(16) float g_KKn[VOCAB * VOCAB]; // NEGATED Gram of k table
__device__ __align__(16) float g_Wcomb[H * H];       // Wout @ Wrp
__device__ __align__(16) float g_bcomb[H];           // Wout @ brp + bout
__device__ unsigned g_bar1 = 0, g_bar2 = 0, g_rst = 0;   // spin barriers

__device__ __forceinline__ float bfly_sum(float v) {
    #pragma unroll
    for (int o = 16; o; o >>= 1) v += __shfl_xor_sync(FULL, v, o);
    return v;
}

// ---- packed f32x2 helpers (sm_103a FFMA2) ----
__device__ __forceinline__ unsigned long long pack2(float lo, float hi) {
    unsigned long long r;
    asm("mov.b64 %0, {%1, %2};" : "=l"(r)
        : "r"(__float_as_uint(lo)), "r"(__float_as_uint(hi)));
    return r;
}
__device__ __forceinline__ void unpack2(unsigned long long p, float& lo, float& hi) {
    unsigned ulo, uhi;
    asm("mov.b64 {%0, %1}, %2;" : "=r"(ulo), "=r"(uhi) : "l"(p));
    lo = __uint_as_float(ulo); hi = __uint_as_float(uhi);
}
__device__ __forceinline__ void fma2(unsigned long long& d,
                                     unsigned long long a, unsigned long long b) {
    asm("fma.rn.f32x2 %0, %1, %2, %0;" : "+l"(d) : "l"(a), "l"(b));
}
__device__ __forceinline__ unsigned long long add2(unsigned long long a,
                                                   unsigned long long b) {
    unsigned long long r;
    asm("add.rn.f32x2 %0, %1, %2;" : "=l"(r) : "l"(a), "l"(b));
    return r;
}

// ======================================================================
// Single fused kernel. grid 64, block 128 (1 warp/SMSP).
// Phase C: stale-gather scan. Next group's d is gathered from smem R
// BEFORE this group's commit (program-order pre-store read) and made
// exact with a 16-term cross-Gram correction. The STS->LDS round-trip
// leaves the critical chain entirely: chain/group ~6 FMA.
// ======================================================================
__global__ void __launch_bounds__(128) fused_kernel(
    const int*   __restrict__ seq,
    const float* __restrict__ embed, const float* __restrict__ W1,
    const float* __restrict__ b1, const float* __restrict__ W2,
    const float* __restrict__ b2, const float* __restrict__ gamma,
    const float* __restrict__ beta, const float* __restrict__ Wk,
    const float* __restrict__ Wv, const float* __restrict__ Wq,
    const float* __restrict__ Wrp, const float* __restrict__ brp,
    const float* __restrict__ Wout, const float* __restrict__ bout,
    float* __restrict__ out)
{
    __shared__ __align__(16) float sKV[VOCAB * 2 * H];    // 32 KB: row id = {k0,k1,v0,v1} x 32 lanes
    __shared__ __align__(16) float sGn[VOCAB * VOCAB];    // 16 KB: negated Gram (scalar)
    __shared__ __align__(16) unsigned char sseq[4][LL];   // 8 KB
    __shared__ __align__(16) float e[H], f1[2 * H], h[H], hs[H];
    __shared__ __align__(16) float sRi[4][H];              // live R per warp
    __shared__ __align__(16) float sMq[4][H];              // Mq handoff
    __shared__ float s_mu, s_rstd, s_kinv;

    const int v    = blockIdx.x;
    const int tid  = threadIdx.x;
    const int lane = tid & 31;
    const int w    = tid >> 5;
    const int lo2  = 2 * lane;
    const int b    = v * 4 + w;

    // ---- stage this block's 4 sequences (warp w stages batch b) ----
    {
        const int4* sg = (const int4*)(seq + b * LL);
        uchar4* ssh = (uchar4*)sseq[w];
        #pragma unroll 4
        for (int i = lane; i < LL / 4; i += 32) {
            int4 t = sg[i];
            ssh[i] = make_uchar4((unsigned char)t.x, (unsigned char)t.y,
                                 (unsigned char)t.z, (unsigned char)t.w);
        }
    }

    // ================= Phase A: encode vocab v =================
    if (tid < H) e[tid] = embed[v * H + tid];
    __syncthreads();

    {   // ff1 = relu(W1 e + b1)
        const float4* w4 = (const float4*)(W1 + tid * H);
        const float4* e4 = (const float4*)e;
        float a0 = 0.f, a1 = 0.f, a2 = 0.f, a3 = 0.f;
        #pragma unroll
        for (int i = 0; i < 16; i++) {
            float4 ww = w4[i], ee = e4[i];
            a0 = fmaf(ww.x, ee.x, a0); a1 = fmaf(ww.y, ee.y, a1);
            a2 = fmaf(ww.z, ee.z, a2); a3 = fmaf(ww.w, ee.w, a3);
        }
        f1[tid] = fmaxf((a0 + a1) + (a2 + a3) + b1[tid], 0.0f);
    }
    __syncthreads();

    if (tid < H) {   // h = e + W2 ff1 + b2
        const float4* w4 = (const float4*)(W2 + tid * 2 * H);
        const float4* f4 = (const float4*)f1;
        float a0 = 0.f, a1 = 0.f, a2 = 0.f, a3 = 0.f;
        float b0 = 0.f, c1 = 0.f, c2 = 0.f, b3 = 0.f;
        #pragma unroll
        for (int i = 0; i < 32; i += 2) {
            float4 ww = w4[i], ff = f4[i];
            a0 = fmaf(ww.x, ff.x, a0); a1 = fmaf(ww.y, ff.y, a1);
            a2 = fmaf(ww.z, ff.z, a2); a3 = fmaf(ww.w, ff.w, a3);
            float4 w2_ = w4[i + 1], ff2 = f4[i + 1];
            b0 = fmaf(w2_.x, ff2.x, b0); c1 = fmaf(w2_.y, ff2.y, c1);
            c2 = fmaf(w2_.z, ff2.z, c2); b3 = fmaf(w2_.w, ff2.w, b3);
        }
        h[tid] = e[tid] + ((a0 + a1) + (a2 + a3)) + ((b0 + c1) + (c2 + b3)) + b2[tid];
    }
    __syncthreads();

    if (tid < 32) {   // LayerNorm stats (biased var, eps 1e-5)
        float x = bfly_sum(h[tid] + h[tid + 32]);
        float mu = x * (1.0f / H);
        float c0 = h[tid] - mu, c1_ = h[tid + 32] - mu;
        float vv = bfly_sum(c0 * c0 + c1_ * c1_);
        if (tid == 0) { s_mu = mu; s_rstd = rsqrtf(vv * (1.0f / H) + 1e-5f); }
    }
    __syncthreads();
    if (tid < H) hs[tid] = (h[tid] - s_mu) * s_rstd * gamma[tid] + beta[tid];
    __syncthreads();

    if (tid < H) {   // k (raw) and q projections
        const float4* wk4 = (const float4*)(Wk + tid * H);
        const float4* wq4 = (const float4*)(Wq + tid * H);
        const float4* h4 = (const float4*)hs;
        float k0 = 0.f, k1 = 0.f, k2 = 0.f, k3 = 0.f;
        float q0 = 0.f, q1 = 0.f, q2 = 0.f, q3 = 0.f;
        #pragma unroll
        for (int i = 0; i < 16; i++) {
            float4 wk = wk4[i], wq = wq4[i], hh = h4[i];
            k0 = fmaf(wk.x, hh.x, k0); k1 = fmaf(wk.y, hh.y, k1);
            k2 = fmaf(wk.z, hh.z, k2); k3 = fmaf(wk.w, hh.w, k3);
            q0 = fmaf(wq.x, hh.x, q0); q1 = fmaf(wq.y, hh.y, q1);
            q2 = fmaf(wq.z, hh.z, q2); q3 = fmaf(wq.w, hh.w, q3);
        }
        h[tid] = (k0 + k1) + (k2 + k3);
        g_qtab[v * H + tid] = (q0 + q1) + (q2 + q3);
    } else {         // v projection
        const int i = tid - H;
        const float4* wv4 = (const float4*)(Wv + i * H);
        const float4* h4 = (const float4*)hs;
        float a0 = 0.f, a1 = 0.f, a2 = 0.f, a3 = 0.f;
        #pragma unroll
        for (int j = 0; j < 16; j++) {
            float4 ww = wv4[j], hh = h4[j];
            a0 = fmaf(ww.x, hh.x, a0); a1 = fmaf(ww.y, hh.y, a1);
            a2 = fmaf(ww.z, hh.z, a2); a3 = fmaf(ww.w, hh.w, a3);
        }
        g_vtab[v * H + i] = (a0 + a1) + (a2 + a3);
    }
    __syncthreads();

    if (tid < 32) {   // k normalization
        float n = bfly_sum(h[tid] * h[tid] + h[tid + 32] * h[tid + 32]);
        if (tid == 0) s_kinv = 1.0f / fmaxf(sqrtf(n), 1e-12f);
    }
    __syncthreads();
    if (tid < H) {
        float kv = h[tid] * s_kinv;
        g_ktab[v * H + tid] = kv;
        hs[tid] = kv;                 // keep own k row in smem for KK phase
    }

    // Wcomb row v + bcomb[v]
    if (tid < H) {
        float ww = 0.f, w1_ = 0.f;
        #pragma unroll
        for (int l = 0; l < H; l += 2) {
            ww  = fmaf(Wout[v * H + l],     Wrp[l * H + tid],       ww);
            w1_ = fmaf(Wout[v * H + l + 1], Wrp[(l + 1) * H + tid], w1_);
        }
        g_Wcomb[v * H + tid] = ww + w1_;
    }
    if (tid == 0) {
        float bb = bout[v], bb1 = 0.f;
        #pragma unroll
        for (int l = 0; l < H; l += 2) {
            bb  = fmaf(Wout[v * H + l],     brp[l],     bb);
            bb1 = fmaf(Wout[v * H + l + 1], brp[l + 1], bb1);
        }
        g_bcomb[v] = bb + bb1;
    }

    // ---- barrier 1: all tables visible ----
    __syncthreads();
    if (tid == 0) {
        __threadfence();
        atomicAdd(&g_bar1, 1u);
        while (atomicAdd(&g_bar1, 0u) < (unsigned)NBLK) { }
        __threadfence();
    }
    __syncthreads();

    // ================= Phase B: negated KK row v =================
    if (tid < H) {
        const int j = tid;
        const float4* kj4 = (const float4*)(g_ktab + j * H);
        const float4* ki4 = (const float4*)hs;
        float a0 = 0.f, a1 = 0.f, a2 = 0.f, a3 = 0.f;
        #pragma unroll
        for (int l = 0; l < 16; l++) {
            float4 ka = ki4[l], kb = __ldg(kj4 + l);
            a0 = fmaf(ka.x, kb.x, a0); a1 = fmaf(ka.y, kb.y, a1);
            a2 = fmaf(ka.z, kb.z, a2); a3 = fmaf(ka.w, kb.w, a3);
        }
        g_KKn[v * H + j] = -((a0 + a1) + (a2 + a3));
    }
    __syncthreads();
    if (tid == 0) { __threadfence(); atomicAdd(&g_bar2, 1u); }

    // ---- R-init: warp w computes batch b, R lives in sRi[w] ----
    {
        const unsigned char* myseq = sseq[w];
        const int qid = myseq[LL - 1];
        const float4* q4 = (const float4*)(g_qtab + qid * H);
        const float4* ka = (const float4*)(g_ktab + lo2 * H);
        const float4* kb = (const float4*)(g_ktab + (lo2 + 1) * H);
        float x0 = 0.f, x1 = 0.f, y0 = 0.f, y1 = 0.f;
        #pragma unroll
        for (int i = 0; i < 16; i += 2) {
            float4 q0 = __ldg(q4 + i),     a0 = __ldg(ka + i),     b0 = __ldg(kb + i);
            float4 q1 = __ldg(q4 + i + 1), a1 = __ldg(ka + i + 1), b1 = __ldg(kb + i + 1);
            x0 = fmaf(a0.x, q0.x, x0); x0 = fmaf(a0.y, q0.y, x0);
            x0 = fmaf(a0.z, q0.z, x0); x0 = fmaf(a0.w, q0.w, x0);
            x1 = fmaf(a1.x, q1.x, x1); x1 = fmaf(a1.y, q1.y, x1);
            x1 = fmaf(a1.z, q1.z, x1); x1 = fmaf(a1.w, q1.w, x1);
            y0 = fmaf(b0.x, q0.x, y0); y0 = fmaf(b0.y, q0.y, y0);
            y0 = fmaf(b0.z, q0.z, y0); y0 = fmaf(b0.w, q0.w, y0);
            y1 = fmaf(b1.x, q1.x, y1); y1 = fmaf(b1.y, q1.y, y1);
            y1 = fmaf(b1.z, q1.z, y1); y1 = fmaf(b1.w, q1.w, y1);
        }
        sRi[w][lo2]     = x0 + x1;
        sRi[w][lo2 + 1] = y0 + y1;
    }

    // ---- barrier 2 wait: all KK rows visible ----
    if (tid == 0) {
        while (atomicAdd(&g_bar2, 0u) < (unsigned)NBLK) { }
        __threadfence();
    }
    __syncthreads();

    // ---- stage scalar Gram + interleaved k|v table ----
    {
        const float4* gg = (const float4*)g_KKn;
        float4* gs = (float4*)sGn;
        #pragma unroll
        for (int i = tid; i < VOCAB * VOCAB / 4; i += 128) gs[i] = __ldg(gg + i);

        float4* kv4 = (float4*)sKV;
        #pragma unroll
        for (int i = tid; i < VOCAB * 32; i += 128) {
            const int row = i >> 5, l = i & 31;
            float2 kp = __ldg((const float2*)&g_KKn[row * H + 2 * l]);
            float2 vp = __ldg((const float2*)&g_vtab[row * H + 2 * l]);
            kv4[i] = make_float4(kp.x, kp.y, vp.x, vp.y);
        }
    }
    __syncthreads();

    // ====== Phase C: stale-gather scan with exact cross-correction ======
    {
        const unsigned char* myseq = sseq[w];
        float* sRw = sRi[w];
        const int kvo = 4 * lane;
        unsigned long long Rp = *(const unsigned long long*)&sRw[lo2];
        unsigned long long Rq = pack2(0.f, 0.f);
        unsigned long long Mp = pack2(0.f, 0.f), Mn = pack2(0.f, 0.f);

        // 3 single steps: t = 2046, 2045, 2044
        #pragma unroll
        for (int t = LL - 2; t >= LL - 4; --t) {
            const int id = (int)myseq[t];
            const float s = sRw[id];
            const ulonglong2 kv = *(const ulonglong2*)&sKV[(id << 7) + kvo];
            const unsigned long long sp = pack2(s, s);
            fma2(Rp, kv.x, sp);
            fma2(Mp, kv.y, sp);
            *(unsigned long long*)&sRw[lo2] = Rp;    // commit (Rq still zero)
            __syncwarp();
        }

        // prologue: group at base = LL-8 (d gathered directly, R current)
        int i0, i1, i2, i3, ri0, ri1, ri2, ri3;
        float G10, G20, G21, G30, G31, G32;
        ulonglong2 KV0, KV1, KV2, KV3;
        float d0, d1, d2, d3;
        {
            const unsigned u = *(const unsigned*)(myseq + (LL - 8));
            i0 = (int)(u >> 24); i1 = (int)((u >> 16) & 0xffu);
            i2 = (int)((u >> 8) & 0xffu); i3 = (int)(u & 0xffu);
            ri0 = i0 << 6; ri1 = i1 << 6; ri2 = i2 << 6; ri3 = i3 << 6;
            G10 = sGn[ri1 + i0];
            G20 = sGn[ri2 + i0]; G21 = sGn[ri2 + i1];
            G30 = sGn[ri3 + i0]; G31 = sGn[ri3 + i1]; G32 = sGn[ri3 + i2];
            KV0 = *(const ulonglong2*)&sKV[(i0 << 7) + kvo];
            KV1 = *(const ulonglong2*)&sKV[(i1 << 7) + kvo];
            KV2 = *(const ulonglong2*)&sKV[(i2 << 7) + kvo];
            KV3 = *(const ulonglong2*)&sKV[(i3 << 7) + kvo];
            d0 = sRw[i0]; d1 = sRw[i1]; d2 = sRw[i2]; d3 = sRw[i3];
        }

        // 511 groups of 4
        #pragma unroll 1
        for (int base = LL - 8; base >= 0; base -= 4) {
            // forward substitution (d already exact for this group)
            const float s0 = d0;
            const float s1 = fmaf(G10, s0, d1);
            const float s2 = fmaf(G21, s1, fmaf(G20, s0, d2));
            const float s3 = fmaf(G32, s2, fmaf(G31, s1, fmaf(G30, s0, d3)));
            const unsigned long long sp0 = pack2(s0, s0);
            const unsigned long long sp1 = pack2(s1, s1);
            const unsigned long long sp2 = pack2(s2, s2);
            const unsigned long long sp3 = pack2(s3, s3);

            // next-group ids
            const int nb = base >= 4 ? base - 4 : 0;
            const unsigned nu = *(const unsigned*)(myseq + nb);
            const int n0 = (int)(nu >> 24), n1 = (int)((nu >> 16) & 0xffu);
            const int n2 = (int)((nu >> 8) & 0xffu), n3 = (int)(nu & 0xffu);
            const int nr0 = n0 << 6, nr1 = n1 << 6, nr2 = n2 << 6, nr3 = n3 << 6;

            // cross-Gram: c[m][j] = Gn[i_m][n_j] (16 LDS, id-dependent only)
            const float c00 = sGn[ri0 + n0], c01 = sGn[ri0 + n1], c02 = sGn[ri0 + n2], c03 = sGn[ri0 + n3];
            const float c10 = sGn[ri1 + n0], c11 = sGn[ri1 + n1], c12 = sGn[ri1 + n2], c13 = sGn[ri1 + n3];
            const float c20 = sGn[ri2 + n0], c21 = sGn[ri2 + n1], c22 = sGn[ri2 + n2], c23 = sGn[ri2 + n3];
            const float c30 = sGn[ri3 + n0], c31 = sGn[ri3 + n1], c32 = sGn[ri3 + n2], c33 = sGn[ri3 + n3];

            // next in-group Gram + kv rows
            const float nG10 = sGn[nr1 + n0];
            const float nG20 = sGn[nr2 + n0], nG21 = sGn[nr2 + n1];
            const float nG30 = sGn[nr3 + n0], nG31 = sGn[nr3 + n1], nG32 = sGn[nr3 + n2];
            const ulonglong2 nKV0 = *(const ulonglong2*)&sKV[(n0 << 7) + kvo];
            const ulonglong2 nKV1 = *(const ulonglong2*)&sKV[(n1 << 7) + kvo];
            const ulonglong2 nKV2 = *(const ulonglong2*)&sKV[(n2 << 7) + kvo];
            const ulonglong2 nKV3 = *(const ulonglong2*)&sKV[(n3 << 7) + kvo];

            // STALE gather: reads R BEFORE this group's commit (pre-store,
            // guaranteed by warp program order on aliasing smem accesses)
            const float rd0 = sRw[n0];
            const float rd1 = sRw[n1];
            const float rd2 = sRw[n2];
            const float rd3 = sRw[n3];

            // R update + lazy commit (off the critical chain now)
            fma2(Rp, KV0.x, sp0);
            fma2(Rq, KV1.x, sp1);
            fma2(Rp, KV2.x, sp2);
            fma2(Rq, KV3.x, sp3);
            *(unsigned long long*)&sRw[lo2] = add2(Rp, Rq);

            // Mq update
            fma2(Mp, KV0.y, sp0);
            fma2(Mn, KV1.y, sp1);
            fma2(Mp, KV2.y, sp2);
            fma2(Mn, KV3.y, sp3);

            // exact correction: d_j(next) = rd_j + sum_m c[m][j]*s_m
            // (s3 term last => chain from s3 is a single FMA)
            d0 = fmaf(c30, s3, fmaf(c20, s2, fmaf(c10, s1, fmaf(c00, s0, rd0))));
            d1 = fmaf(c31, s3, fmaf(c21, s2, fmaf(c11, s1, fmaf(c01, s0, rd1))));
            d2 = fmaf(c32, s3, fmaf(c22, s2, fmaf(c12, s1, fmaf(c02, s0, rd2))));
            d3 = fmaf(c33, s3, fmaf(c23, s2, fmaf(c13, s1, fmaf(c03, s0, rd3))));

            // rotate
            i0 = n0; i1 = n1; i2 = n2; i3 = n3;
            ri0 = nr0; ri1 = nr1; ri2 = nr2; ri3 = nr3;
            G10 = nG10; G20 = nG20; G21 = nG21;
            G30 = nG30; G31 = nG31; G32 = nG32;
            KV0 = nKV0; KV1 = nKV1; KV2 = nKV2; KV3 = nKV3;

            asm volatile("" ::: "memory");
        }

        float M0, M1;
        unpack2(add2(Mp, Mn), M0, M1);
        sMq[w][lo2]     = M0;
        sMq[w][lo2 + 1] = M1;
    }
    __syncwarp();

    // ---- epilogue: out = Wcomb @ Mq + bcomb ----
    #pragma unroll
    for (int rr = 0; rr < 2; rr++) {
        const int i = lane + 32 * rr;
        const float4* w4 = (const float4*)(g_Wcomb + i * H);
        const float4* m4 = (const float4*)sMq[w];
        float a0 = 0.f, a1 = 0.f, a2 = 0.f, a3 = 0.f;
        #pragma unroll
        for (int j = 0; j < 16; j++) {
            float4 ww = __ldg(w4 + j);
            float4 m = m4[j];
            a0 = fmaf(ww.x, m.x, a0); a1 = fmaf(ww.y, m.y, a1);
            a2 = fmaf(ww.z, m.z, a2); a3 = fmaf(ww.w, m.w, a3);
        }
        out[b * H + i] = (a0 + a1) + (a2 + a3) + g_bcomb[i];
    }

    // ---- reset spin barriers for the next (graph-replayed) launch ----
    __syncthreads();
    if (tid == 0) {
        __threadfence();
        if (atomicAdd(&g_rst, 1u) == (unsigned)(NBLK - 1)) {
            atomicExch(&g_bar1, 0u);
            atomicExch(&g_bar2, 0u);
            atomicExch(&g_rst, 0u);
        }
    }
}

// ======================================================================
extern "C" void kernel_launch(void* const* d_in, const int* in_sizes, int n_in,
                              void* d_out, int out_size)
{
    (void)in_sizes; (void)n_in; (void)out_size;
    const int*   seq   = (const int*)  d_in[0];
    const float* embed = (const float*)d_in[1];
    const float* W1    = (const float*)d_in[2];
    const float* b1    = (const float*)d_in[3];
    const float* W2    = (const float*)d_in[4];
    const float* b2    = (const float*)d_in[5];
    const float* gamma = (const float*)d_in[6];
    const float* beta  = (const float*)d_in[7];
    const float* Wk    = (const float*)d_in[8];
    const float* Wv    = (const float*)d_in[9];
    const float* Wq    = (const float*)d_in[10];
    const float* Wrp   = (const float*)d_in[11];
    const float* brp   = (const float*)d_in[12];
    const float* Wout  = (const float*)d_in[13];
    const float* bout  = (const float*)d_in[14];

    fused_kernel<<<NBLK, 128>>>(seq, embed, W1, b1, W2, b2, gamma, beta,
                                Wk, Wv, Wq, Wrp, brp, Wout, bout,
                                (float*)d_out);
}

// round 16
// speedup vs baseline: 1.3715x; 1.3715x over previous
#include <cuda_runtime.h>

#define H  64
#define LL 2048
#define VOCAB 64
#define NBLK 64
#define FULL 0xffffffffu

// -------- device-global scratch (no runtime allocation allowed) --------
__device__ __align__(16) float g_ktab[VOCAB * H];    // normalized k per vocab id
__device__ __align__(16) float g_vtab[VOCAB * H];    // v per vocab id
__device__ __align__(16) float g_qtab[VOCAB * H];    // q per vocab id
__device__ __align__(16) float g_KKn[VOCAB * VOCAB]; // NEGATED Gram of k table
__device__ __align__(16) float g_Wcomb[H * H];       // Wout @ Wrp
__device__ __align__(16) float g_bcomb[H];           // Wout @ brp + bout
__device__ unsigned g_bar1 = 0, g_bar2 = 0, g_rst = 0;   // spin barriers

__device__ __forceinline__ float bfly_sum(float v) {
    #pragma unroll
    for (int o = 16; o; o >>= 1) v += __shfl_xor_sync(FULL, v, o);
    return v;
}

// ---- packed f32x2 helpers (sm_103a FFMA2) ----
__device__ __forceinline__ unsigned long long pack2(float lo, float hi) {
    unsigned long long r;
    asm("mov.b64 %0, {%1, %2};" : "=l"(r)
        : "r"(__float_as_uint(lo)), "r"(__float_as_uint(hi)));
    return r;
}
__device__ __forceinline__ void unpack2(unsigned long long p, float& lo, float& hi) {
    unsigned ulo, uhi;
    asm("mov.b64 {%0, %1}, %2;" : "=r"(ulo), "=r"(uhi) : "l"(p));
    lo = __uint_as_float(ulo); hi = __uint_as_float(uhi);
}
__device__ __forceinline__ void fma2(unsigned long long& d,
                                     unsigned long long a, unsigned long long b) {
    asm("fma.rn.f32x2 %0, %1, %2, %0;" : "+l"(d) : "l"(a), "l"(b));
}
__device__ __forceinline__ unsigned long long add2(unsigned long long a,
                                                   unsigned long long b) {
    unsigned long long r;
    asm("add.rn.f32x2 %0, %1, %2;" : "=l"(r) : "l"(a), "l"(b));
    return r;
}

// ======================================================================
// Single fused kernel. grid 64, block 128 (1 warp/SMSP).
// Phase C: R12's proven SHFL-free C=4 scan with ONE delta — the per-group
// __syncwarp is removed (fence-only commit; correctness proven in R14).
// ======================================================================
__global__ void __launch_bounds__(128) fused_kernel(
    const int*   __restrict__ seq,
    const float* __restrict__ embed, const float* __restrict__ W1,
    const float* __restrict__ b1, const float* __restrict__ W2,
    const float* __restrict__ b2, const float* __restrict__ gamma,
    const float* __restrict__ beta, const float* __restrict__ Wk,
    const float* __restrict__ Wv, const float* __restrict__ Wq,
    const float* __restrict__ Wrp, const float* __restrict__ brp,
    const float* __restrict__ Wout, const float* __restrict__ bout,
    float* __restrict__ out)
{
    __shared__ __align__(16) float sKV[VOCAB * 2 * H];    // 32 KB: row id = {k0,k1,v0,v1} x 32 lanes
    __shared__ __align__(16) float sGn[VOCAB * VOCAB];    // 16 KB: negated Gram (scalar)
    __shared__ __align__(16) unsigned char sseq[4][LL];   // 8 KB
    __shared__ __align__(16) float e[H], f1[2 * H], h[H], hs[H];
    __shared__ __align__(16) float sRi[4][H];              // live R per warp
    __shared__ __align__(16) float sMq[4][H];              // Mq handoff
    __shared__ float s_mu, s_rstd, s_kinv;

    const int v    = blockIdx.x;
    const int tid  = threadIdx.x;
    const int lane = tid & 31;
    const int w    = tid >> 5;
    const int lo2  = 2 * lane;
    const int b    = v * 4 + w;

    // ---- stage this block's 4 sequences (warp w stages batch b) ----
    {
        const int4* sg = (const int4*)(seq + b * LL);
        uchar4* ssh = (uchar4*)sseq[w];
        #pragma unroll 4
        for (int i = lane; i < LL / 4; i += 32) {
            int4 t = sg[i];
            ssh[i] = make_uchar4((unsigned char)t.x, (unsigned char)t.y,
                                 (unsigned char)t.z, (unsigned char)t.w);
        }
    }

    // ================= Phase A: encode vocab v =================
    if (tid < H) e[tid] = embed[v * H + tid];
    __syncthreads();

    {   // ff1 = relu(W1 e + b1)
        const float4* w4 = (const float4*)(W1 + tid * H);
        const float4* e4 = (const float4*)e;
        float a0 = 0.f, a1 = 0.f, a2 = 0.f, a3 = 0.f;
        #pragma unroll
        for (int i = 0; i < 16; i++) {
            float4 ww = w4[i], ee = e4[i];
            a0 = fmaf(ww.x, ee.x, a0); a1 = fmaf(ww.y, ee.y, a1);
            a2 = fmaf(ww.z, ee.z, a2); a3 = fmaf(ww.w, ee.w, a3);
        }
        f1[tid] = fmaxf((a0 + a1) + (a2 + a3) + b1[tid], 0.0f);
    }
    __syncthreads();

    if (tid < H) {   // h = e + W2 ff1 + b2
        const float4* w4 = (const float4*)(W2 + tid * 2 * H);
        const float4* f4 = (const float4*)f1;
        float a0 = 0.f, a1 = 0.f, a2 = 0.f, a3 = 0.f;
        float b0 = 0.f, c1 = 0.f, c2 = 0.f, b3 = 0.f;
        #pragma unroll
        for (int i = 0; i < 32; i += 2) {
            float4 ww = w4[i], ff = f4[i];
            a0 = fmaf(ww.x, ff.x, a0); a1 = fmaf(ww.y, ff.y, a1);
            a2 = fmaf(ww.z, ff.z, a2); a3 = fmaf(ww.w, ff.w, a3);
            float4 w2_ = w4[i + 1], ff2 = f4[i + 1];
            b0 = fmaf(w2_.x, ff2.x, b0); c1 = fmaf(w2_.y, ff2.y, c1);
            c2 = fmaf(w2_.z, ff2.z, c2); b3 = fmaf(w2_.w, ff2.w, b3);
        }
        h[tid] = e[tid] + ((a0 + a1) + (a2 + a3)) + ((b0 + c1) + (c2 + b3)) + b2[tid];
    }
    __syncthreads();

    if (tid < 32) {   // LayerNorm stats (biased var, eps 1e-5)
        float x = bfly_sum(h[tid] + h[tid + 32]);
        float mu = x * (1.0f / H);
        float c0 = h[tid] - mu, c1_ = h[tid + 32] - mu;
        float vv = bfly_sum(c0 * c0 + c1_ * c1_);
        if (tid == 0) { s_mu = mu; s_rstd = rsqrtf(vv * (1.0f / H) + 1e-5f); }
    }
    __syncthreads();
    if (tid < H) hs[tid] = (h[tid] - s_mu) * s_rstd * gamma[tid] + beta[tid];
    __syncthreads();

    if (tid < H) {   // k (raw) and q projections
        const float4* wk4 = (const float4*)(Wk + tid * H);
        const float4* wq4 = (const float4*)(Wq + tid * H);
        const float4* h4 = (const float4*)hs;
        float k0 = 0.f, k1 = 0.f, k2 = 0.f, k3 = 0.f;
        float q0 = 0.f, q1 = 0.f, q2 = 0.f, q3 = 0.f;
        #pragma unroll
        for (int i = 0; i < 16; i++) {
            float4 wk = wk4[i], wq = wq4[i], hh = h4[i];
            k0 = fmaf(wk.x, hh.x, k0); k1 = fmaf(wk.y, hh.y, k1);
            k2 = fmaf(wk.z, hh.z, k2); k3 = fmaf(wk.w, hh.w, k3);
            q0 = fmaf(wq.x, hh.x, q0); q1 = fmaf(wq.y, hh.y, q1);
            q2 = fmaf(wq.z, hh.z, q2); q3 = fmaf(wq.w, hh.w, q3);
        }
        h[tid] = (k0 + k1) + (k2 + k3);
        g_qtab[v * H + tid] = (q0 + q1) + (q2 + q3);
    } else {         // v projection
        const int i = tid - H;
        const float4* wv4 = (const float4*)(Wv + i * H);
        const float4* h4 = (const float4*)hs;
        float a0 = 0.f, a1 = 0.f, a2 = 0.f, a3 = 0.f;
        #pragma unroll
        for (int j = 0; j < 16; j++) {
            float4 ww = wv4[j], hh = h4[j];
            a0 = fmaf(ww.x, hh.x, a0); a1 = fmaf(ww.y, hh.y, a1);
            a2 = fmaf(ww.z, hh.z, a2); a3 = fmaf(ww.w, hh.w, a3);
        }
        g_vtab[v * H + i] = (a0 + a1) + (a2 + a3);
    }
    __syncthreads();

    if (tid < 32) {   // k normalization
        float n = bfly_sum(h[tid] * h[tid] + h[tid + 32] * h[tid + 32]);
        if (tid == 0) s_kinv = 1.0f / fmaxf(sqrtf(n), 1e-12f);
    }
    __syncthreads();
    if (tid < H) {
        float kv = h[tid] * s_kinv;
        g_ktab[v * H + tid] = kv;
        hs[tid] = kv;                 // keep own k row in smem for KK phase
    }

    // Wcomb row v + bcomb[v]
    if (tid < H) {
        float ww = 0.f, w1_ = 0.f;
        #pragma unroll
        for (int l = 0; l < H; l += 2) {
            ww  = fmaf(Wout[v * H + l],     Wrp[l * H + tid],       ww);
            w1_ = fmaf(Wout[v * H + l + 1], Wrp[(l + 1) * H + tid], w1_);
        }
        g_Wcomb[v * H + tid] = ww + w1_;
    }
    if (tid == 0) {
        float bb = bout[v], bb1 = 0.f;
        #pragma unroll
        for (int l = 0; l < H; l += 2) {
            bb  = fmaf(Wout[v * H + l],     brp[l],     bb);
            bb1 = fmaf(Wout[v * H + l + 1], brp[l + 1], bb1);
        }
        g_bcomb[v] = bb + bb1;
    }

    // ---- barrier 1: all tables visible ----
    __syncthreads();
    if (tid == 0) {
        __threadfence();
        atomicAdd(&g_bar1, 1u);
        while (atomicAdd(&g_bar1, 0u) < (unsigned)NBLK) { }
        __threadfence();
    }
    __syncthreads();

    // ================= Phase B: negated KK row v =================
    if (tid < H) {
        const int j = tid;
        const float4* kj4 = (const float4*)(g_ktab + j * H);
        const float4* ki4 = (const float4*)hs;
        float a0 = 0.f, a1 = 0.f, a2 = 0.f, a3 = 0.f;
        #pragma unroll
        for (int l = 0; l < 16; l++) {
            float4 ka = ki4[l], kb = __ldg(kj4 + l);
            a0 = fmaf(ka.x, kb.x, a0); a1 = fmaf(ka.y, kb.y, a1);
            a2 = fmaf(ka.z, kb.z, a2); a3 = fmaf(ka.w, kb.w, a3);
        }
        g_KKn[v * H + j] = -((a0 + a1) + (a2 + a3));
    }
    __syncthreads();
    if (tid == 0) { __threadfence(); atomicAdd(&g_bar2, 1u); }

    // ---- R-init: warp w computes batch b, R lives in sRi[w] ----
    {
        const unsigned char* myseq = sseq[w];
        const int qid = myseq[LL - 1];
        const float4* q4 = (const float4*)(g_qtab + qid * H);
        const float4* ka = (const float4*)(g_ktab + lo2 * H);
        const float4* kb = (const float4*)(g_ktab + (lo2 + 1) * H);
        float x0 = 0.f, x1 = 0.f, y0 = 0.f, y1 = 0.f;
        #pragma unroll
        for (int i = 0; i < 16; i += 2) {
            float4 q0 = __ldg(q4 + i),     a0 = __ldg(ka + i),     b0 = __ldg(kb + i);
            float4 q1 = __ldg(q4 + i + 1), a1 = __ldg(ka + i + 1), b1 = __ldg(kb + i + 1);
            x0 = fmaf(a0.x, q0.x, x0); x0 = fmaf(a0.y, q0.y, x0);
            x0 = fmaf(a0.z, q0.z, x0); x0 = fmaf(a0.w, q0.w, x0);
            x1 = fmaf(a1.x, q1.x, x1); x1 = fmaf(a1.y, q1.y, x1);
            x1 = fmaf(a1.z, q1.z, x1); x1 = fmaf(a1.w, q1.w, x1);
            y0 = fmaf(b0.x, q0.x, y0); y0 = fmaf(b0.y, q0.y, y0);
            y0 = fmaf(b0.z, q0.z, y0); y0 = fmaf(b0.w, q0.w, y0);
            y1 = fmaf(b1.x, q1.x, y1); y1 = fmaf(b1.y, q1.y, y1);
            y1 = fmaf(b1.z, q1.z, y1); y1 = fmaf(b1.w, q1.w, y1);
        }
        sRi[w][lo2]     = x0 + x1;
        sRi[w][lo2 + 1] = y0 + y1;
    }

    // ---- barrier 2 wait: all KK rows visible ----
    if (tid == 0) {
        while (atomicAdd(&g_bar2, 0u) < (unsigned)NBLK) { }
        __threadfence();
    }
    __syncthreads();

    // ---- stage scalar Gram + interleaved k|v table ----
    {
        const float4* gg = (const float4*)g_KKn;
        float4* gs = (float4*)sGn;
        #pragma unroll
        for (int i = tid; i < VOCAB * VOCAB / 4; i += 128) gs[i] = __ldg(gg + i);

        float4* kv4 = (float4*)sKV;
        #pragma unroll
        for (int i = tid; i < VOCAB * 32; i += 128) {
            const int row = i >> 5, l = i & 31;
            float2 kp = __ldg((const float2*)&g_KKn[row * H + 2 * l]);
            float2 vp = __ldg((const float2*)&g_vtab[row * H + 2 * l]);
            kv4[i] = make_float4(kp.x, kp.y, vp.x, vp.y);
        }
    }
    __syncthreads();

    // ====== Phase C: R12 scan, fence-only commit (no per-group syncwarp) ======
    {
        const unsigned char* myseq = sseq[w];
        float* sRw = sRi[w];
        const int kvo = 4 * lane;
        unsigned long long Rp = *(const unsigned long long*)&sRw[lo2];
        unsigned long long Rq = pack2(0.f, 0.f);
        unsigned long long Mp = pack2(0.f, 0.f), Mn = pack2(0.f, 0.f);

        // 3 single steps: t = 2046, 2045, 2044
        #pragma unroll
        for (int t = LL - 2; t >= LL - 4; --t) {
            const int id = (int)myseq[t];
            const float s = sRw[id];                 // broadcast LDS
            const ulonglong2 kv = *(const ulonglong2*)&sKV[(id << 7) + kvo];
            const unsigned long long sp = pack2(s, s);
            fma2(Rp, kv.x, sp);
            fma2(Mp, kv.y, sp);
            *(unsigned long long*)&sRw[lo2] = Rp;    // commit (Rq still zero)
            asm volatile("" ::: "memory");           // order STS before next gather
        }

        // 511 groups of 4 with id prefetch
        unsigned ids = *(const unsigned*)(myseq + (LL - 8));
        #pragma unroll 1
        for (int base = LL - 8; base >= 0; base -= 4) {
            const int id0 = (int)(ids >> 24);           // t = base+3 (largest)
            const int id1 = (int)((ids >> 16) & 0xffu);
            const int id2 = (int)((ids >> 8) & 0xffu);
            const int id3 = (int)(ids & 0xffu);
            const int r0 = id0 << 6, r1 = id1 << 6, r2 = id2 << 6, r3 = id3 << 6;

            // gathers d_j = R[id_j] — pipelined broadcast LDS (no SHFL)
            const float d0 = sRw[id0];
            const float d1 = sRw[id1];
            const float d2 = sRw[id2];
            const float d3 = sRw[id3];

            // loads fill the gather shadow (independent of R)
            const float g10 = sGn[r1 + id0];
            const float g20 = sGn[r2 + id0], g21 = sGn[r2 + id1];
            const float g30 = sGn[r3 + id0], g31 = sGn[r3 + id1], g32 = sGn[r3 + id2];
            const ulonglong2 kv0 = *(const ulonglong2*)&sKV[(id0 << 7) + kvo];
            const ulonglong2 kv1 = *(const ulonglong2*)&sKV[(id1 << 7) + kvo];
            const ulonglong2 kv2 = *(const ulonglong2*)&sKV[(id2 << 7) + kvo];
            const ulonglong2 kv3 = *(const ulonglong2*)&sKV[(id3 << 7) + kvo];
            ids = *(const unsigned*)(myseq + (base >= 4 ? base - 4 : 0));

            // forward substitution (negated Gram -> pure FMA)
            const float s0 = d0;
            const float s1 = fmaf(g10, s0, d1);
            const float s2 = fmaf(g21, s1, fmaf(g20, s0, d2));
            const float s3 = fmaf(g32, s2, fmaf(g31, s1, fmaf(g30, s0, d3)));
            const unsigned long long sp0 = pack2(s0, s0);
            const unsigned long long sp1 = pack2(s1, s1);
            const unsigned long long sp2 = pack2(s2, s2);
            const unsigned long long sp3 = pack2(s3, s3);

            // R update: dual accumulators, commit sum
            fma2(Rp, kv0.x, sp0);
            fma2(Rq, kv1.x, sp1);
            fma2(Rp, kv2.x, sp2);
            fma2(Rq, kv3.x, sp3);
            *(unsigned long long*)&sRw[lo2] = add2(Rp, Rq);

            // Mq update fills the STS->LDS visibility window
            fma2(Mp, kv0.y, sp0);
            fma2(Mn, kv1.y, sp1);
            fma2(Mp, kv2.y, sp2);
            fma2(Mn, kv3.y, sp3);

            asm volatile("" ::: "memory");           // order STS before next gather
        }

        float M0, M1;
        unpack2(add2(Mp, Mn), M0, M1);
        sMq[w][lo2]     = M0;
        sMq[w][lo2 + 1] = M1;
    }
    __syncwarp();

    // ---- epilogue: out = Wcomb @ Mq + bcomb ----
    #pragma unroll
    for (int rr = 0; rr < 2; rr++) {
        const int i = lane + 32 * rr;
        const float4* w4 = (const float4*)(g_Wcomb + i * H);
        const float4* m4 = (const float4*)sMq[w];
        float a0 = 0.f, a1 = 0.f, a2 = 0.f, a3 = 0.f;
        #pragma unroll
        for (int j = 0; j < 16; j++) {
            float4 ww = __ldg(w4 + j);
            float4 m = m4[j];
            a0 = fmaf(ww.x, m.x, a0); a1 = fmaf(ww.y, m.y, a1);
            a2 = fmaf(ww.z, m.z, a2); a3 = fmaf(ww.w, m.w, a3);
        }
        out[b * H + i] = (a0 + a1) + (a2 + a3) + g_bcomb[i];
    }

    // ---- reset spin barriers for the next (graph-replayed) launch ----
    __syncthreads();
    if (tid == 0) {
        __threadfence();
        if (atomicAdd(&g_rst, 1u) == (unsigned)(NBLK - 1)) {
            atomicExch(&g_bar1, 0u);
            atomicExch(&g_bar2, 0u);
            atomicExch(&g_rst, 0u);
        }
    }
}

// ======================================================================
extern "C" void kernel_launch(void* const* d_in, const int* in_sizes, int n_in,
                              void* d_out, int out_size)
{
    (void)in_sizes; (void)n_in; (void)out_size;
    const int*   seq   = (const int*)  d_in[0];
    const float* embed = (const float*)d_in[1];
    const float* W1    = (const float*)d_in[2];
    const float* b1    = (const float*)d_in[3];
    const float* W2    = (const float*)d_in[4];
    const float* b2    = (const float*)d_in[5];
    const float* gamma = (const float*)d_in[6];
    const float* beta  = (const float*)d_in[7];
    const float* Wk    = (const float*)d_in[8];
    const float* Wv    = (const float*)d_in[9];
    const float* Wq    = (const float*)d_in[10];
    const float* Wrp   = (const float*)d_in[11];
    const float* brp   = (const float*)d_in[12];
    const float* Wout  = (const float*)d_in[13];
    const float* bout  = (const float*)d_in[14];

    fused_kernel<<<NBLK, 128>>>(seq, embed, W1, b1, W2, b2, gamma, beta,
                                Wk, Wv, Wq, Wrp, brp, Wout, bout,
                                (float*)d_out);
}